// round 17
// baseline (speedup 1.0000x reference)
#include <cuda_runtime.h>
#include <math.h>

// DiffJPEG forward: persistent, double-buffered, pipelined kernel.
// A': per-(block,row) thread: load+color+row-FDCT -> T1 (transposed)
// B : octet per block: col-FDCT, quant, col-IDCT -> T2
// C': per-(block,row) thread: row-IDCT x3 + color out
// Schedule: B(t) | barrier | A'(t+1)^buf ++ C'(t) (disjoint warps) | barrier.
// img: (16,3,512,512) f32, quality: int scalar, out: (16,3,512,512) f32.

#define IMG_W 512
#define IMG_H 512
#define BATCH 16
#define NTHREADS 768
#define NTASKS 2048                        // batch * 64 strips * 2 halves
#define NRESIDENT 296                      // 148 SMs * 2 CTAs
// 96 units (3 ch * 32 blocks); slot = unit*72 + (a>>2)*36 + (a&3)*8 + b
#define BUF_FLOATS (96 * 72)               // 6912
#define SMEM_FLOATS (2 * BUF_FLOATS)
#define SMEM_BYTES  (SMEM_FLOATS * 4)      // 55296

#define MAGIC 12582912.0f                  // 1.5 * 2^23: round-to-nearest-even

#define CA  0.35355339059327373f
#define CB1 0.46193976625564337f
#define CB3 0.19134171618254492f
#define CD1 0.49039264020161522f
#define CD3 0.41573480615127262f
#define CD5 0.27778511650980114f
#define CD7 0.09754516100806413f

#define FDCT8(x0,x1,x2,x3,x4,x5,x6,x7) do {                                  \
    float e0=(x0)+(x7), e1=(x1)+(x6), e2=(x2)+(x5), e3=(x3)+(x4);            \
    float o0=(x0)-(x7), o1=(x1)-(x6), o2=(x2)-(x5), o3=(x3)-(x4);            \
    float ee0=e0+e3, ee1=e1+e2, eo0=e0-e3, eo1=e1-e2;                        \
    (x0) = CA*(ee0+ee1);                                                     \
    (x4) = CA*(ee0-ee1);                                                     \
    (x2) = CB1*eo0 + CB3*eo1;                                                \
    (x6) = CB3*eo0 - CB1*eo1;                                                \
    (x1) = CD1*o0 + CD3*o1 + CD5*o2 + CD7*o3;                                \
    (x3) = CD3*o0 - CD7*o1 - CD1*o2 - CD5*o3;                                \
    (x5) = CD5*o0 - CD1*o1 + CD7*o2 + CD3*o3;                                \
    (x7) = CD7*o0 - CD5*o1 + CD3*o2 - CD1*o3;                                \
} while(0)

#define IDCT8(x0,x1,x2,x3,x4,x5,x6,x7) do {                                  \
    float ee0 = CA*((x0)+(x4)), ee1 = CA*((x0)-(x4));                        \
    float eo0 = CB1*(x2) + CB3*(x6), eo1 = CB3*(x2) - CB1*(x6);              \
    float o0 = CD1*(x1) + CD3*(x3) + CD5*(x5) + CD7*(x7);                    \
    float o1 = CD3*(x1) - CD7*(x3) - CD1*(x5) - CD5*(x7);                    \
    float o2 = CD5*(x1) - CD1*(x3) + CD7*(x5) + CD3*(x7);                    \
    float o3 = CD7*(x1) - CD5*(x3) + CD3*(x5) - CD1*(x7);                    \
    float e0=ee0+eo0, e3=ee0-eo0, e1=ee1+eo1, e2=ee1-eo1;                    \
    (x0)=e0+o0; (x7)=e0-o0; (x1)=e1+o1; (x6)=e1-o1;                          \
    (x2)=e2+o2; (x5)=e2-o2; (x3)=e3+o3; (x4)=e3-o3;                          \
} while(0)

__constant__ float c_lum[64] = {
    16, 11, 10, 16, 24, 40, 51, 61,
    12, 12, 14, 19, 26, 58, 60, 55,
    14, 13, 16, 24, 40, 57, 69, 56,
    14, 17, 22, 29, 51, 87, 80, 62,
    18, 22, 37, 56, 68, 109, 103, 77,
    24, 35, 55, 64, 81, 104, 113, 92,
    49, 64, 78, 87, 103, 121, 120, 101,
    72, 92, 95, 98, 112, 100, 103, 99
};
__constant__ float c_chrom[64] = {
    17, 18, 24, 47, 99, 99, 99, 99,
    18, 21, 26, 66, 99, 99, 99, 99,
    24, 26, 56, 99, 99, 99, 99, 99,
    47, 66, 99, 99, 99, 99, 99, 99,
    99, 99, 99, 99, 99, 99, 99, 99,
    99, 99, 99, 99, 99, 99, 99, 99,
    99, 99, 99, 99, 99, 99, 99, 99,
    99, 99, 99, 99, 99, 99, 99, 99
};

__global__ void __launch_bounds__(NTHREADS, 2)
jpeg_kernel(const float* __restrict__ img,
            const int* __restrict__ quality,
            float* __restrict__ out)
{
    extern __shared__ float sm[];
    __shared__ __align__(16) float qzipL[160];
    __shared__ __align__(16) float qzipC[160];

    const int tid = threadIdx.x;

    if (tid < 256) {
        int t = tid >> 7;
        int rem = tid & 127;
        int l = rem >> 4;
        int kp = (rem >> 2) & 3;
        int comp = rem & 3;
        int k = 2 * kp + (comp >> 1);
        int q = *quality;
        q = max(1, min(100, q));
        float scale = (q < 50) ? (5000.0f / (float)q) : (200.0f - 2.0f * (float)q);
        float base = t ? c_chrom[k * 8 + l] : c_lum[k * 8 + l];
        float v = (base * scale + 50.0f) / 100.0f;
        v = fminf(fmaxf(v, 1.0f), 255.0f);
        float outv = (comp & 1) ? (1.0f / v) : v;
        (t ? qzipC : qzipL)[(l * 5 + kp) * 4 + comp] = outv;
    }

    const size_t CH = (size_t)IMG_H * IMG_W;

    // octet decomposition for B (task-invariant)
    const int unit = tid >> 3;          // 0..95 = c*32 + blk
    const int r = tid & 7;
    const int c = unit >> 5;
    const int roff = unit * 72 + (r >> 2) * 36 + (r & 3) * 8;

    // A' (tid<256) and C' (tid>=512) both use per-(block,row) decomposition
    // on their local index: blk = li>>3, rr = li&7.

    auto phaseA = [&](int task, float* buf) {
        if (tid < 256) {
            int blk = tid >> 3, rr = tid & 7;
            int b = task >> 7;
            int rem = task & 127;
            int row = (rem >> 1) * 8 + rr;
            int col = ((rem & 1) << 8) + blk * 8;
            size_t off = (size_t)b * 3 * CH + (size_t)row * IMG_W + col;
            float4 R0 = *(const float4*)(img + off);
            float4 R1 = *(const float4*)(img + off + 4);
            float4 G0 = *(const float4*)(img + off + CH);
            float4 G1 = *(const float4*)(img + off + CH + 4);
            float4 B0 = *(const float4*)(img + off + 2 * CH);
            float4 B1 = *(const float4*)(img + off + 2 * CH + 4);
            float Rv[8] = {R0.x,R0.y,R0.z,R0.w,R1.x,R1.y,R1.z,R1.w};
            float Gv[8] = {G0.x,G0.y,G0.z,G0.w,G1.x,G1.y,G1.z,G1.w};
            float Bv[8] = {B0.x,B0.y,B0.z,B0.w,B1.x,B1.y,B1.z,B1.w};
            int trbase = blk * 72 + rr;    // T1 transposed base (channel 0)
            float t[8];

            // Y
            #pragma unroll
            for (int j = 0; j < 8; j++)
                t[j] = fmaf(76.245f, Rv[j], fmaf(149.685f, Gv[j], 29.07f * Bv[j]));
            FDCT8(t[0],t[1],t[2],t[3],t[4],t[5],t[6],t[7]);
            #pragma unroll
            for (int l = 0; l < 8; l++)
                buf[trbase + (l >> 2) * 36 + (l & 3) * 8] = t[l];

            // Cb
            #pragma unroll
            for (int j = 0; j < 8; j++)
                t[j] = fmaf(-43.0185f, Rv[j], fmaf(-84.4815f, Gv[j], fmaf(127.5f, Bv[j], 128.0f)));
            FDCT8(t[0],t[1],t[2],t[3],t[4],t[5],t[6],t[7]);
            #pragma unroll
            for (int l = 0; l < 8; l++)
                buf[32 * 72 + trbase + (l >> 2) * 36 + (l & 3) * 8] = t[l];

            // Cr
            #pragma unroll
            for (int j = 0; j < 8; j++)
                t[j] = fmaf(127.5f, Rv[j], fmaf(-106.7685f, Gv[j], fmaf(-20.7315f, Bv[j], 128.0f)));
            FDCT8(t[0],t[1],t[2],t[3],t[4],t[5],t[6],t[7]);
            #pragma unroll
            for (int l = 0; l < 8; l++)
                buf[64 * 72 + trbase + (l >> 2) * 36 + (l & 3) * 8] = t[l];
        }
    };

    auto phaseC = [&](int task, const float* buf) {
        if (tid >= 512) {
            int li = tid - 512;
            int blk = li >> 3, rr = li & 7;
            int b = task >> 7;
            int rem = task & 127;
            int row = (rem >> 1) * 8 + rr;
            int col = ((rem & 1) << 8) + blk * 8;
            int rb = blk * 72 + (rr >> 2) * 36 + (rr & 3) * 8;

            float Y[8], Cb[8], Cr[8];
            {
                float4 a = *(const float4*)(buf + rb);
                float4 d = *(const float4*)(buf + rb + 4);
                Y[0]=a.x; Y[1]=a.y; Y[2]=a.z; Y[3]=a.w;
                Y[4]=d.x; Y[5]=d.y; Y[6]=d.z; Y[7]=d.w;
                a = *(const float4*)(buf + 32 * 72 + rb);
                d = *(const float4*)(buf + 32 * 72 + rb + 4);
                Cb[0]=a.x; Cb[1]=a.y; Cb[2]=a.z; Cb[3]=a.w;
                Cb[4]=d.x; Cb[5]=d.y; Cb[6]=d.z; Cb[7]=d.w;
                a = *(const float4*)(buf + 64 * 72 + rb);
                d = *(const float4*)(buf + 64 * 72 + rb + 4);
                Cr[0]=a.x; Cr[1]=a.y; Cr[2]=a.z; Cr[3]=a.w;
                Cr[4]=d.x; Cr[5]=d.y; Cr[6]=d.z; Cr[7]=d.w;
            }
            IDCT8(Y[0],Y[1],Y[2],Y[3],Y[4],Y[5],Y[6],Y[7]);
            IDCT8(Cb[0],Cb[1],Cb[2],Cb[3],Cb[4],Cb[5],Cb[6],Cb[7]);
            IDCT8(Cr[0],Cr[1],Cr[2],Cr[3],Cr[4],Cr[5],Cr[6],Cr[7]);

            float R[8], G[8], B[8];
            #pragma unroll
            for (int j = 0; j < 8; j++) {
                float y  = Y[j];
                float cb = Cb[j] - 128.0f;
                float cr = Cr[j] - 128.0f;
                float rr2 = y + 1.402f * cr;
                float gg = y - 0.34414f * cb - 0.71414f * cr;
                float bb = y + 1.772f * cb;
                R[j] = fminf(fmaxf(rr2 * (1.0f / 255.0f), 0.0f), 1.0f);
                G[j] = fminf(fmaxf(gg * (1.0f / 255.0f), 0.0f), 1.0f);
                B[j] = fminf(fmaxf(bb * (1.0f / 255.0f), 0.0f), 1.0f);
            }
            size_t off = (size_t)b * 3 * CH + (size_t)row * IMG_W + col;
            *(float4*)(out + off)              = make_float4(R[0],R[1],R[2],R[3]);
            *(float4*)(out + off + 4)          = make_float4(R[4],R[5],R[6],R[7]);
            *(float4*)(out + off + CH)         = make_float4(G[0],G[1],G[2],G[3]);
            *(float4*)(out + off + CH + 4)     = make_float4(G[4],G[5],G[6],G[7]);
            *(float4*)(out + off + 2*CH)       = make_float4(B[0],B[1],B[2],B[3]);
            *(float4*)(out + off + 2*CH + 4)   = make_float4(B[4],B[5],B[6],B[7]);
        }
    };

    int task = blockIdx.x;
    if (task >= NTASKS) return;

    int p = 0;
    phaseA(task, sm);            // prologue fill of buffer 0
    __syncthreads();             // also orders qzip init

    while (true) {
        float* buf = sm + p * BUF_FLOATS;
        float* const ub = buf + unit * 72;
        float* const rp = buf + roff;

        // ---- Phase B(task): octet; col-FDCT, quant, col-IDCT only ----
        {
            const int b = task >> 7;
            // load my T1 column (l = r), contiguous over spatial row index
            float y0,y1,y2,y3,y4,y5,y6,y7;
            {
                float4 v0 = *(const float4*)(rp);
                float4 v1 = *(const float4*)(rp + 4);
                y0=v0.x; y1=v0.y; y2=v0.z; y3=v0.w;
                y4=v1.x; y5=v1.y; y6=v1.z; y7=v1.w;
            }
            FDCT8(y0,y1,y2,y3,y4,y5,y6,y7);   // -> D[k][l=r]

            if (r == 0) y0 -= 1024.0f;        // -128 shift commutes to DC

            {
                const float* qz = ((b * 3 + c) < BATCH) ? qzipL : qzipC;
                const float4* zl = (const float4*)(qz + r * 20);  // l = r
                float4 z;
                z = zl[0];
                { float t0=fmaf(y0,z.y,MAGIC), t1=fmaf(y1,z.w,MAGIC);
                  y0=__fadd_rn(t0,-MAGIC)*z.x; y1=__fadd_rn(t1,-MAGIC)*z.z; }
                z = zl[1];
                { float t0=fmaf(y2,z.y,MAGIC), t1=fmaf(y3,z.w,MAGIC);
                  y2=__fadd_rn(t0,-MAGIC)*z.x; y3=__fadd_rn(t1,-MAGIC)*z.z; }
                z = zl[2];
                { float t0=fmaf(y4,z.y,MAGIC), t1=fmaf(y5,z.w,MAGIC);
                  y4=__fadd_rn(t0,-MAGIC)*z.x; y5=__fadd_rn(t1,-MAGIC)*z.z; }
                z = zl[3];
                { float t0=fmaf(y6,z.y,MAGIC), t1=fmaf(y7,z.w,MAGIC);
                  y6=__fadd_rn(t0,-MAGIC)*z.x; y7=__fadd_rn(t1,-MAGIC)*z.z; }
            }

            if (r == 0) y0 += 1024.0f;        // +128 shift commutes to DC

            IDCT8(y0,y1,y2,y3,y4,y5,y6,y7);   // -> T2[i][l=r]

            __syncwarp();   // all octet lanes done reading T1 before T2 store
            ub[0*36 + 0*8 + r] = y0;
            ub[0*36 + 1*8 + r] = y1;
            ub[0*36 + 2*8 + r] = y2;
            ub[0*36 + 3*8 + r] = y3;
            ub[1*36 + 0*8 + r] = y4;
            ub[1*36 + 1*8 + r] = y5;
            ub[1*36 + 2*8 + r] = y6;
            ub[1*36 + 3*8 + r] = y7;
        }
        __syncthreads();

        // ---- A'(next) into other buffer (tids 0-255) concurrently with
        //      C'(task) from this buffer (tids 512-767) ----
        int tn = task + NRESIDENT;
        if (tn < NTASKS) {
            phaseA(tn, sm + (p ^ 1) * BUF_FLOATS);
            phaseC(task, buf);
            task = tn;
            p ^= 1;
            __syncthreads();
        } else {
            phaseC(task, buf);
            break;
        }
    }
}

extern "C" void kernel_launch(void* const* d_in, const int* in_sizes, int n_in,
                              void* d_out, int out_size)
{
    const float* img = (const float*)d_in[0];
    const int* quality = (const int*)d_in[1];
    float* out = (float*)d_out;

    cudaFuncSetAttribute(jpeg_kernel,
                         cudaFuncAttributeMaxDynamicSharedMemorySize,
                         SMEM_BYTES);

    dim3 grid(NRESIDENT);   // 296 persistent CTAs
    jpeg_kernel<<<grid, NTHREADS, SMEM_BYTES>>>(img, quality, out);
}